// round 2
// baseline (speedup 1.0000x reference)
#include <cuda_runtime.h>
#include <cstdint>

// Problem constants (fixed by the reference): B=4, C=64, H=W=128, O=64, K=3, pad=1, stride=1
#define BATCH 4
#define CH    64
#define HH    128
#define WW    128
#define HW    (HH*WW)         // 16384
#define NPIX  (BATCH*HW)      // 65536
#define OCH   64
#define KK    9
#define OFFC  18              // 2*KK offset channels

// Scratch (no cudaMalloc allowed): NHWC-transposed x and NCHW offsets
__device__ __align__(16) float g_xt[BATCH * HW * CH];      // 16 MB, [b][y][x][c]
__device__ __align__(16) float g_off[BATCH * OFFC * HW];   // 4.7 MB, [b][j][y][x]

// ---------------- f32x2 packed helpers ----------------
static __device__ __forceinline__ unsigned long long pk(float lo, float hi) {
    unsigned long long r;
    asm("mov.b64 %0, {%1, %2};" : "=l"(r)
        : "r"(__float_as_uint(lo)), "r"(__float_as_uint(hi)));
    return r;
}
static __device__ __forceinline__ void upk(unsigned long long v, float& lo, float& hi) {
    unsigned int a, b;
    asm("mov.b64 {%0, %1}, %2;" : "=r"(a), "=r"(b) : "l"(v));
    lo = __uint_as_float(a); hi = __uint_as_float(b);
}
static __device__ __forceinline__ unsigned long long f2fma(unsigned long long a,
                                                          unsigned long long b,
                                                          unsigned long long c) {
    unsigned long long d;
    asm("fma.rn.f32x2 %0, %1, %2, %3;" : "=l"(d) : "l"(a), "l"(b), "l"(c));
    return d;
}
static __device__ __forceinline__ unsigned long long f2mul(unsigned long long a,
                                                          unsigned long long b) {
    unsigned long long d;
    asm("mul.rn.f32x2 %0, %1, %2;" : "=l"(d) : "l"(a), "l"(b));
    return d;
}

// ---------------- Kernel 0: NCHW -> NHWC transpose of x ----------------
// Block = 256 threads handles 32 consecutive pixels of one batch, all 64 channels.
__global__ void k_transpose(const float* __restrict__ x) {
    __shared__ float tile[8][33];
    int bid = blockIdx.x;
    int b  = bid >> 9;            // 512 blocks per batch image
    int p0 = (bid & 511) << 5;    // 32 pixels
    int tx = threadIdx.x & 31, ty = threadIdx.x >> 5;   // read map: ty = channel-sub
    int cx = threadIdx.x & 7,  pw = threadIdx.x >> 3;   // write map
    for (int c0 = 0; c0 < CH; c0 += 8) {
        tile[ty][tx] = x[(((size_t)(b * CH + c0 + ty)) << 14) + p0 + tx];
        __syncthreads();
        g_xt[(((size_t)((b << 14) + p0 + pw)) << 6) + c0 + cx] = tile[cx][pw];
        __syncthreads();
    }
}

// ---------------- Kernel 1: offset conv (3x3, 64->18) ----------------
// One thread per output pixel; all 18 offset channels as 9 f32x2 accumulators.
__global__ __launch_bounds__(128) void k_offset(const float* __restrict__ offw,
                                                const float* __restrict__ offb) {
    // packed weights: ws2[k][c][j2] = (offw[2*j2][c][k], offw[2*j2+1][c][k])
    __shared__ __align__(16) unsigned long long ws2[KK * CH * 9];   // 41.5 KB
    for (int idx = threadIdx.x; idx < KK * CH * 9; idx += 128) {
        int k = idx / 576, r = idx % 576, c = r / 9, j2 = r % 9;
        float w0 = offw[((2 * j2) * CH + c) * 9 + k];
        float w1 = offw[((2 * j2 + 1) * CH + c) * 9 + k];
        ws2[idx] = pk(w0, w1);
    }
    __syncthreads();

    int p   = blockIdx.x * 128 + threadIdx.x;
    int b   = p >> 14, pix = p & 16383;
    int y   = pix >> 7, x = pix & 127;

    unsigned long long acc[9];
#pragma unroll
    for (int j2 = 0; j2 < 9; j2++) acc[j2] = pk(offb[2 * j2], offb[2 * j2 + 1]);

#pragma unroll 1
    for (int k = 0; k < KK; k++) {
        int iy = y + k / 3 - 1, ix = x + k % 3 - 1;
        if ((unsigned)iy < (unsigned)HH && (unsigned)ix < (unsigned)WW) {
            const ulonglong2* src = (const ulonglong2*)
                (g_xt + (((size_t)((b << 14) + (iy << 7) + ix)) << 6));
            const unsigned long long* wk = ws2 + k * 576;
#pragma unroll 4
            for (int c4 = 0; c4 < 16; c4++) {
                ulonglong2 q = src[c4];
                float v0, v1, v2, v3;
                upk(q.x, v0, v1); upk(q.y, v2, v3);
                const unsigned long long* w0p = wk + (c4 * 4 + 0) * 9;
                const unsigned long long* w1p = wk + (c4 * 4 + 1) * 9;
                const unsigned long long* w2p = wk + (c4 * 4 + 2) * 9;
                const unsigned long long* w3p = wk + (c4 * 4 + 3) * 9;
                unsigned long long vv;
                vv = pk(v0, v0);
#pragma unroll
                for (int j2 = 0; j2 < 9; j2++) acc[j2] = f2fma(vv, w0p[j2], acc[j2]);
                vv = pk(v1, v1);
#pragma unroll
                for (int j2 = 0; j2 < 9; j2++) acc[j2] = f2fma(vv, w1p[j2], acc[j2]);
                vv = pk(v2, v2);
#pragma unroll
                for (int j2 = 0; j2 < 9; j2++) acc[j2] = f2fma(vv, w2p[j2], acc[j2]);
                vv = pk(v3, v3);
#pragma unroll
                for (int j2 = 0; j2 < 9; j2++) acc[j2] = f2fma(vv, w3p[j2], acc[j2]);
            }
        }
    }
#pragma unroll
    for (int j2 = 0; j2 < 9; j2++) {
        float lo, hi; upk(acc[j2], lo, hi);
        g_off[(((size_t)(b * OFFC + 2 * j2)) << 14) + pix]     = lo;
        g_off[(((size_t)(b * OFFC + 2 * j2 + 1)) << 14) + pix] = hi;
    }
}

// ---------------- Kernel 2: deformable conv ----------------
// One thread per output pixel, all 64 output channels as 32 f32x2 accumulators.
// Per tap: stage packed weight tile [c][o2] in smem, bilinear-sample 64 channels
// from NHWC x (4 corner ulonglong2 loads per 4 channels), rank-1 update via f32x2.
__global__ __launch_bounds__(128) void k_deform(const float* __restrict__ weight,
                                                const float* __restrict__ bias,
                                                float* __restrict__ out) {
    __shared__ __align__(16) unsigned long long W2s[CH * 32];   // 16 KB per tap

    int p   = blockIdx.x * 128 + threadIdx.x;
    int b   = p >> 14, pix = p & 16383;
    int y   = pix >> 7, x = pix & 127;

    unsigned long long acc[32];
#pragma unroll
    for (int o2 = 0; o2 < 32; o2++) acc[o2] = pk(bias[2 * o2], bias[2 * o2 + 1]);

    const float* offp = g_off + (((size_t)b * OFFC) << 14) + pix;
    const float* xb   = g_xt + ((size_t)b << 20);   // b * HW * CH

#pragma unroll 1
    for (int k = 0; k < KK; k++) {
        __syncthreads();
        for (int idx = threadIdx.x; idx < CH * 32; idx += 128) {
            int c = idx >> 5, o2 = idx & 31;
            float w0 = weight[((2 * o2) * CH + c) * 9 + k];
            float w1 = weight[((2 * o2 + 1) * CH + c) * 9 + k];
            W2s[idx] = pk(w0, w1);
        }
        __syncthreads();

        float py = (float)(y + k / 3 - 1) + offp[(size_t)(2 * k) << 14];
        float px = (float)(x + k % 3 - 1) + offp[(size_t)(2 * k + 1) << 14];
        float fy0 = floorf(py), fx0 = floorf(px);
        int y0 = (int)fy0, x0 = (int)fx0;
        int y1 = y0 + 1,   x1 = x0 + 1;
        float wy1 = py - fy0, wx1 = px - fx0;
        float wy0 = 1.f - wy1, wx0 = 1.f - wx1;
        bool vy0 = (unsigned)y0 < (unsigned)HH, vy1 = (unsigned)y1 < (unsigned)HH;
        bool vx0 = (unsigned)x0 < (unsigned)WW, vx1 = (unsigned)x1 < (unsigned)WW;
        float w00 = (vy0 && vx0) ? wy0 * wx0 : 0.f;
        float w01 = (vy0 && vx1) ? wy0 * wx1 : 0.f;
        float w10 = (vy1 && vx0) ? wy1 * wx0 : 0.f;
        float w11 = (vy1 && vx1) ? wy1 * wx1 : 0.f;
        int cy0 = min(max(y0, 0), HH - 1), cy1 = min(max(y1, 0), HH - 1);
        int cx0 = min(max(x0, 0), WW - 1), cx1 = min(max(x1, 0), WW - 1);

        const ulonglong2* p00 = (const ulonglong2*)(xb + (size_t)((cy0 << 7) + cx0) * CH);
        const ulonglong2* p01 = (const ulonglong2*)(xb + (size_t)((cy0 << 7) + cx1) * CH);
        const ulonglong2* p10 = (const ulonglong2*)(xb + (size_t)((cy1 << 7) + cx0) * CH);
        const ulonglong2* p11 = (const ulonglong2*)(xb + (size_t)((cy1 << 7) + cx1) * CH);

        unsigned long long W00p = pk(w00, w00), W01p = pk(w01, w01);
        unsigned long long W10p = pk(w10, w10), W11p = pk(w11, w11);

#pragma unroll 2
        for (int c4 = 0; c4 < 16; c4++) {
            ulonglong2 a = p00[c4], bq = p01[c4], cq = p10[c4], dq = p11[c4];
            unsigned long long vlo =
                f2fma(W11p, dq.x, f2fma(W10p, cq.x, f2fma(W01p, bq.x, f2mul(W00p, a.x))));
            unsigned long long vhi =
                f2fma(W11p, dq.y, f2fma(W10p, cq.y, f2fma(W01p, bq.y, f2mul(W00p, a.y))));
            float v0, v1, v2, v3;
            upk(vlo, v0, v1); upk(vhi, v2, v3);
#pragma unroll
            for (int cc = 0; cc < 4; cc++) {
                float v = (cc == 0) ? v0 : (cc == 1) ? v1 : (cc == 2) ? v2 : v3;
                unsigned long long vv = pk(v, v);
                const ulonglong2* wr = (const ulonglong2*)(W2s + (size_t)(c4 * 4 + cc) * 32);
#pragma unroll
                for (int t = 0; t < 16; t++) {
                    ulonglong2 ww = wr[t];
                    acc[2 * t]     = f2fma(vv, ww.x, acc[2 * t]);
                    acc[2 * t + 1] = f2fma(vv, ww.y, acc[2 * t + 1]);
                }
            }
        }
    }

#pragma unroll
    for (int o2 = 0; o2 < 32; o2++) {
        float lo, hi; upk(acc[o2], lo, hi);
        out[(((size_t)((b << 6) + 2 * o2)) << 14) + pix]     = lo;
        out[(((size_t)((b << 6) + 2 * o2 + 1)) << 14) + pix] = hi;
    }
}

extern "C" void kernel_launch(void* const* d_in, const int* in_sizes, int n_in,
                              void* d_out, int out_size) {
    const float* x      = (const float*)d_in[0];
    const float* offw   = (const float*)d_in[1];
    const float* offb   = (const float*)d_in[2];
    const float* weight = (const float*)d_in[3];
    const float* bias   = (const float*)d_in[4];
    float* out = (float*)d_out;

    k_transpose<<<2048, 256>>>(x);
    k_offset<<<NPIX / 128, 128>>>(offw, offb);
    k_deform<<<NPIX / 128, 128>>>(weight, bias, out);
}

// round 3
// speedup vs baseline: 2.1172x; 2.1172x over previous
#include <cuda_runtime.h>
#include <cstdint>

// B=4, C=64, H=W=128, O=64, K=3, pad=1, stride=1
#define BATCH 4
#define CH    64
#define HH    128
#define WW    128
#define HW    16384
#define NPIX  65536
#define OCH   64
#define KK    9

// Scratch (__device__ globals; no cudaMalloc allowed)
__device__ __align__(16) float g_xt[BATCH * HW * CH];   // NHWC x, 16 MB
__device__ __align__(16) float g_off[NPIX * 20];        // pixel-major offsets (18 used, 2 pad)
__device__ __align__(16) float g_wt[KK * CH * OCH];     // weight transposed [k][c][oc]

// ---------------- f32x2 packed helpers ----------------
typedef unsigned long long ull;
static __device__ __forceinline__ ull pk(float lo, float hi) {
    ull r;
    asm("mov.b64 %0, {%1, %2};" : "=l"(r)
        : "r"(__float_as_uint(lo)), "r"(__float_as_uint(hi)));
    return r;
}
static __device__ __forceinline__ void upk(ull v, float& lo, float& hi) {
    unsigned int a, b;
    asm("mov.b64 {%0, %1}, %2;" : "=r"(a), "=r"(b) : "l"(v));
    lo = __uint_as_float(a); hi = __uint_as_float(b);
}
static __device__ __forceinline__ ull f2fma(ull a, ull b, ull c) {
    ull d;
    asm("fma.rn.f32x2 %0, %1, %2, %3;" : "=l"(d) : "l"(a), "l"(b), "l"(c));
    return d;
}
static __device__ __forceinline__ ull f2mul(ull a, ull b) {
    ull d;
    asm("mul.rn.f32x2 %0, %1, %2;" : "=l"(d) : "l"(a), "l"(b));
    return d;
}

// ---------------- Kernel 0: NCHW -> NHWC transpose of x ----------------
__global__ void k_transpose(const float* __restrict__ x) {
    __shared__ float tile[8][33];
    int bid = blockIdx.x;
    int b  = bid >> 9;
    int p0 = (bid & 511) << 5;
    int tx = threadIdx.x & 31, ty = threadIdx.x >> 5;
    int cx = threadIdx.x & 7,  pw = threadIdx.x >> 3;
    for (int c0 = 0; c0 < CH; c0 += 8) {
        tile[ty][tx] = x[(((size_t)(b * CH + c0 + ty)) << 14) + p0 + tx];
        __syncthreads();
        g_xt[(((size_t)((b << 14) + p0 + pw)) << 6) + c0 + cx] = tile[cx][pw];
        __syncthreads();
    }
}

// ---------------- Kernel 0b: weight transpose -> [k][c][oc] ----------------
__global__ void k_wtrans(const float* __restrict__ w) {
    int i = blockIdx.x * 256 + threadIdx.x;
    if (i < KK * CH * OCH) {
        int k = i / (CH * OCH), r = i % (CH * OCH);
        int c = r >> 6, oc = r & 63;
        g_wt[i] = w[(oc * CH + c) * KK + k];
    }
}

// ---------------- Kernel 1: offset conv (3x3, 64->18), reads NCHW x ----------------
// Thread per output pixel. Lanes = consecutive x -> all x loads coalesced; rows L1-reused.
__global__ __launch_bounds__(128) void k_offset(const float* __restrict__ x,
                                                const float* __restrict__ offw,
                                                const float* __restrict__ offb) {
    __shared__ __align__(16) ull ws2[KK * CH * 9];   // [k][c][j2] packed pairs
    for (int idx = threadIdx.x; idx < KK * CH * 9; idx += 128) {
        int k = idx / 576, r = idx % 576, c = r / 9, j2 = r % 9;
        float w0 = offw[((2 * j2) * CH + c) * 9 + k];
        float w1 = offw[((2 * j2 + 1) * CH + c) * 9 + k];
        ws2[idx] = pk(w0, w1);
    }
    __syncthreads();

    int p   = blockIdx.x * 128 + threadIdx.x;
    int b   = p >> 14, pix = p & 16383;
    int y   = pix >> 7, xx = pix & 127;

    ull acc[9];
#pragma unroll
    for (int j2 = 0; j2 < 9; j2++) acc[j2] = pk(offb[2 * j2], offb[2 * j2 + 1]);

    const float* xb = x + ((size_t)b << 20);   // b * CH * HW

#pragma unroll 1
    for (int k = 0; k < KK; k++) {
        int iy = y + k / 3 - 1, ix = xx + k % 3 - 1;
        if ((unsigned)iy < (unsigned)HH && (unsigned)ix < (unsigned)WW) {
            const float* src = xb + (iy << 7) + ix;   // + c<<14 per channel
            const ull* wk = ws2 + k * 576;
#pragma unroll 4
            for (int c4 = 0; c4 < 16; c4++) {
                float v0 = src[(size_t)(c4 * 4 + 0) << 14];
                float v1 = src[(size_t)(c4 * 4 + 1) << 14];
                float v2 = src[(size_t)(c4 * 4 + 2) << 14];
                float v3 = src[(size_t)(c4 * 4 + 3) << 14];
                const ull* w0p = wk + (c4 * 4 + 0) * 9;
                const ull* w1p = wk + (c4 * 4 + 1) * 9;
                const ull* w2p = wk + (c4 * 4 + 2) * 9;
                const ull* w3p = wk + (c4 * 4 + 3) * 9;
                ull vv;
                vv = pk(v0, v0);
#pragma unroll
                for (int j2 = 0; j2 < 9; j2++) acc[j2] = f2fma(vv, w0p[j2], acc[j2]);
                vv = pk(v1, v1);
#pragma unroll
                for (int j2 = 0; j2 < 9; j2++) acc[j2] = f2fma(vv, w1p[j2], acc[j2]);
                vv = pk(v2, v2);
#pragma unroll
                for (int j2 = 0; j2 < 9; j2++) acc[j2] = f2fma(vv, w2p[j2], acc[j2]);
                vv = pk(v3, v3);
#pragma unroll
                for (int j2 = 0; j2 < 9; j2++) acc[j2] = f2fma(vv, w3p[j2], acc[j2]);
            }
        }
    }
    // pixel-major output: g_off[p*20 + 2k..2k+1]
    float2* op = (float2*)(g_off + (size_t)p * 20);
#pragma unroll
    for (int j2 = 0; j2 < 9; j2++) {
        float lo, hi; upk(acc[j2], lo, hi);
        op[j2] = make_float2(lo, hi);
    }
}

// ---------------- Kernel 2: deformable conv, tiled + staged ----------------
// Block = one image row (128 px), 256 threads. Per tap: setup -> coalesced gather
// into smem val tile -> register-blocked (8px x 4oc) f32x2 rank update.
__global__ __launch_bounds__(256, 2) void k_deform(const float* __restrict__ bias,
                                                   float* __restrict__ out) {
    __shared__ __align__(16) float s_pool[128 * 68];  // val[px][c] (pad 68) / out staging
    __shared__ float s_set[8][128];                   // per-tap bilinear setup, comp-major

    int t  = threadIdx.x;
    int bx = blockIdx.x;
    int b  = bx >> 7, y = bx & 127;
    int pix0 = y << 7;

    const float* xb = g_xt + ((size_t)b << 20);
    int pxg = t >> 4;        // 16 pixel-groups of 8
    int ocg = t & 15;        // 16 oc-groups of 4

    ull acc[8][2];
    {
        ull b01 = pk(bias[ocg * 4 + 0], bias[ocg * 4 + 1]);
        ull b23 = pk(bias[ocg * 4 + 2], bias[ocg * 4 + 3]);
#pragma unroll
        for (int p = 0; p < 8; p++) { acc[p][0] = b01; acc[p][1] = b23; }
    }

    const float* offbase = g_off + (size_t)((b << 14) + pix0) * 20;

#pragma unroll 1
    for (int k = 0; k < KK; k++) {
        __syncthreads();
        // ---- stage A: bilinear setup (one thread per pixel) ----
        if (t < 128) {
            float2 o = *(const float2*)(offbase + t * 20 + 2 * k);
            float py  = (float)(y + k / 3 - 1) + o.x;
            float pxf = (float)(t + k % 3 - 1) + o.y;
            float fy0 = floorf(py), fx0 = floorf(pxf);
            int y0 = (int)fy0, x0 = (int)fx0;
            int y1 = y0 + 1,   x1 = x0 + 1;
            float wy1 = py - fy0, wx1 = pxf - fx0;
            float wy0 = 1.f - wy1, wx0 = 1.f - wx1;
            bool vy0 = (unsigned)y0 < (unsigned)HH, vy1 = (unsigned)y1 < (unsigned)HH;
            bool vx0 = (unsigned)x0 < (unsigned)WW, vx1 = (unsigned)x1 < (unsigned)WW;
            s_set[0][t] = (vy0 && vx0) ? wy0 * wx0 : 0.f;
            s_set[1][t] = (vy0 && vx1) ? wy0 * wx1 : 0.f;
            s_set[2][t] = (vy1 && vx0) ? wy1 * wx0 : 0.f;
            s_set[3][t] = (vy1 && vx1) ? wy1 * wx1 : 0.f;
            int cy0 = min(max(y0, 0), HH - 1), cy1 = min(max(y1, 0), HH - 1);
            int cx0 = min(max(x0, 0), WW - 1), cx1 = min(max(x1, 0), WW - 1);
            s_set[4][t] = __int_as_float(((cy0 << 7) + cx0) << 6);
            s_set[5][t] = __int_as_float(((cy0 << 7) + cx1) << 6);
            s_set[6][t] = __int_as_float(((cy1 << 7) + cx0) << 6);
            s_set[7][t] = __int_as_float(((cy1 << 7) + cx1) << 6);
        }
        __syncthreads();
        // ---- stage B: coalesced gather + blend into val tile ----
#pragma unroll
        for (int it = 0; it < 8; it++) {
            int slot = it * 256 + t;
            int pxl = slot >> 4, cg = slot & 15;
            float w00 = s_set[0][pxl], w01 = s_set[1][pxl];
            float w10 = s_set[2][pxl], w11 = s_set[3][pxl];
            int i00 = __float_as_int(s_set[4][pxl]);
            int i01 = __float_as_int(s_set[5][pxl]);
            int i10 = __float_as_int(s_set[6][pxl]);
            int i11 = __float_as_int(s_set[7][pxl]);
            ulonglong2 A = *((const ulonglong2*)(xb + i00) + cg);
            ulonglong2 Bq = *((const ulonglong2*)(xb + i01) + cg);
            ulonglong2 Cq = *((const ulonglong2*)(xb + i10) + cg);
            ulonglong2 D = *((const ulonglong2*)(xb + i11) + cg);
            ull W00 = pk(w00, w00), W01 = pk(w01, w01);
            ull W10 = pk(w10, w10), W11 = pk(w11, w11);
            ulonglong2 r;
            r.x = f2fma(W11, D.x, f2fma(W10, Cq.x, f2fma(W01, Bq.x, f2mul(W00, A.x))));
            r.y = f2fma(W11, D.y, f2fma(W10, Cq.y, f2fma(W01, Bq.y, f2mul(W00, A.y))));
            *(ulonglong2*)&s_pool[pxl * 68 + cg * 4] = r;
        }
        __syncthreads();
        // ---- stage C: register-blocked rank update (8 px x 4 oc per thread) ----
        const ulonglong2* wkp = (const ulonglong2*)(g_wt + k * 4096) + ocg;  // + c*16
#pragma unroll 1
        for (int c4 = 0; c4 < 16; c4++) {
            float4 v[8];
#pragma unroll
            for (int p = 0; p < 8; p++)
                v[p] = *(const float4*)&s_pool[(pxg * 8 + p) * 68 + c4 * 4];
            ulonglong2 wq0 = wkp[(c4 * 4 + 0) * 16];
            ulonglong2 wq1 = wkp[(c4 * 4 + 1) * 16];
            ulonglong2 wq2 = wkp[(c4 * 4 + 2) * 16];
            ulonglong2 wq3 = wkp[(c4 * 4 + 3) * 16];
#pragma unroll
            for (int p = 0; p < 8; p++) {
                ull vp;
                vp = pk(v[p].x, v[p].x);
                acc[p][0] = f2fma(vp, wq0.x, acc[p][0]);
                acc[p][1] = f2fma(vp, wq0.y, acc[p][1]);
                vp = pk(v[p].y, v[p].y);
                acc[p][0] = f2fma(vp, wq1.x, acc[p][0]);
                acc[p][1] = f2fma(vp, wq1.y, acc[p][1]);
                vp = pk(v[p].z, v[p].z);
                acc[p][0] = f2fma(vp, wq2.x, acc[p][0]);
                acc[p][1] = f2fma(vp, wq2.y, acc[p][1]);
                vp = pk(v[p].w, v[p].w);
                acc[p][0] = f2fma(vp, wq3.x, acc[p][0]);
                acc[p][1] = f2fma(vp, wq3.y, acc[p][1]);
            }
        }
    }

    // ---- epilogue: transpose through smem, coalesced NCHW stores ----
    __syncthreads();
#pragma unroll
    for (int p = 0; p < 8; p++) {
        int px = pxg * 8 + p;
        float o0, o1, o2, o3;
        upk(acc[p][0], o0, o1);
        upk(acc[p][1], o2, o3);
        s_pool[(ocg * 4 + 0) * 133 + px] = o0;
        s_pool[(ocg * 4 + 1) * 133 + px] = o1;
        s_pool[(ocg * 4 + 2) * 133 + px] = o2;
        s_pool[(ocg * 4 + 3) * 133 + px] = o3;
    }
    __syncthreads();
    float* ob = out + (((size_t)b << 6) << 14) + pix0;
#pragma unroll
    for (int it = 0; it < 32; it++) {
        int idx = it * 256 + t;
        int oc = idx >> 7, px = idx & 127;
        ob[((size_t)oc << 14) + px] = s_pool[oc * 133 + px];
    }
}

extern "C" void kernel_launch(void* const* d_in, const int* in_sizes, int n_in,
                              void* d_out, int out_size) {
    const float* x      = (const float*)d_in[0];
    const float* offw   = (const float*)d_in[1];
    const float* offb   = (const float*)d_in[2];
    const float* weight = (const float*)d_in[3];
    const float* bias   = (const float*)d_in[4];
    float* out = (float*)d_out;

    k_transpose<<<2048, 256>>>(x);
    k_wtrans<<<(KK * CH * OCH + 255) / 256, 256>>>(weight);
    k_offset<<<NPIX / 128, 128>>>(x, offw, offb);
    k_deform<<<512, 256>>>(bias, out);
}

// round 4
// speedup vs baseline: 2.1258x; 1.0040x over previous
#include <cuda_runtime.h>
#include <cstdint>

// B=4, C=64, H=W=128, O=64, K=3, pad=1, stride=1
#define BATCH 4
#define CH    64
#define HH    128
#define WW    128
#define HW    16384
#define NPIX  65536
#define OCH   64
#define KK    9

// Scratch (__device__ globals; no cudaMalloc allowed)
__device__ __align__(16) float g_xt[BATCH * HW * CH];   // NHWC x, 16 MB
__device__ __align__(16) float g_off[NPIX * 20];        // pixel-major offsets (18 used, 2 pad)
__device__ __align__(16) float g_wt[KK * CH * OCH];     // weight transposed [k][c][oc]

typedef unsigned long long ull;
static __device__ __forceinline__ ull pk(float lo, float hi) {
    ull r;
    asm("mov.b64 %0, {%1, %2};" : "=l"(r)
        : "r"(__float_as_uint(lo)), "r"(__float_as_uint(hi)));
    return r;
}
static __device__ __forceinline__ void upk(ull v, float& lo, float& hi) {
    unsigned int a, b;
    asm("mov.b64 {%0, %1}, %2;" : "=r"(a), "=r"(b) : "l"(v));
    lo = __uint_as_float(a); hi = __uint_as_float(b);
}
static __device__ __forceinline__ ull f2fma(ull a, ull b, ull c) {
    ull d;
    asm("fma.rn.f32x2 %0, %1, %2, %3;" : "=l"(d) : "l"(a), "l"(b), "l"(c));
    return d;
}

// ---------------- Kernel 0: NCHW -> NHWC transpose of x ----------------
__global__ void k_transpose(const float* __restrict__ x) {
    __shared__ float tile[8][33];
    int bid = blockIdx.x;
    int b  = bid >> 9;
    int p0 = (bid & 511) << 5;
    int tx = threadIdx.x & 31, ty = threadIdx.x >> 5;
    int cx = threadIdx.x & 7,  pw = threadIdx.x >> 3;
    for (int c0 = 0; c0 < CH; c0 += 8) {
        tile[ty][tx] = x[(((size_t)(b * CH + c0 + ty)) << 14) + p0 + tx];
        __syncthreads();
        g_xt[(((size_t)((b << 14) + p0 + pw)) << 6) + c0 + cx] = tile[cx][pw];
        __syncthreads();
    }
}

// ---------------- Kernel 0b: weight transpose -> [k][c][oc] ----------------
__global__ void k_wtrans(const float* __restrict__ w) {
    int i = blockIdx.x * 256 + threadIdx.x;
    if (i < KK * CH * OCH) {
        int k = i / (CH * OCH), r = i % (CH * OCH);
        int c = r >> 6, oc = r & 63;
        g_wt[i] = w[(oc * CH + c) * KK + k];
    }
}

// ---------------- Kernel 1: offset conv (3x3, 64->18), reads NCHW x ----------------
__global__ __launch_bounds__(128) void k_offset(const float* __restrict__ x,
                                                const float* __restrict__ offw,
                                                const float* __restrict__ offb) {
    __shared__ __align__(16) ull ws2[KK * CH * 9];   // [k][c][j2] packed pairs
    for (int idx = threadIdx.x; idx < KK * CH * 9; idx += 128) {
        int k = idx / 576, r = idx % 576, c = r / 9, j2 = r % 9;
        float w0 = offw[((2 * j2) * CH + c) * 9 + k];
        float w1 = offw[((2 * j2 + 1) * CH + c) * 9 + k];
        ws2[idx] = pk(w0, w1);
    }
    __syncthreads();

    int p   = blockIdx.x * 128 + threadIdx.x;
    int b   = p >> 14, pix = p & 16383;
    int y   = pix >> 7, xx = pix & 127;

    ull acc[9];
#pragma unroll
    for (int j2 = 0; j2 < 9; j2++) acc[j2] = pk(offb[2 * j2], offb[2 * j2 + 1]);

    const float* xb = x + ((size_t)b << 20);

#pragma unroll 1
    for (int k = 0; k < KK; k++) {
        int iy = y + k / 3 - 1, ix = xx + k % 3 - 1;
        if ((unsigned)iy < (unsigned)HH && (unsigned)ix < (unsigned)WW) {
            const float* src = xb + (iy << 7) + ix;
            const ull* wk = ws2 + k * 576;
#pragma unroll 4
            for (int c4 = 0; c4 < 16; c4++) {
                float v0 = src[(size_t)(c4 * 4 + 0) << 14];
                float v1 = src[(size_t)(c4 * 4 + 1) << 14];
                float v2 = src[(size_t)(c4 * 4 + 2) << 14];
                float v3 = src[(size_t)(c4 * 4 + 3) << 14];
                const ull* w0p = wk + (c4 * 4 + 0) * 9;
                const ull* w1p = wk + (c4 * 4 + 1) * 9;
                const ull* w2p = wk + (c4 * 4 + 2) * 9;
                const ull* w3p = wk + (c4 * 4 + 3) * 9;
                ull vv;
                vv = pk(v0, v0);
#pragma unroll
                for (int j2 = 0; j2 < 9; j2++) acc[j2] = f2fma(vv, w0p[j2], acc[j2]);
                vv = pk(v1, v1);
#pragma unroll
                for (int j2 = 0; j2 < 9; j2++) acc[j2] = f2fma(vv, w1p[j2], acc[j2]);
                vv = pk(v2, v2);
#pragma unroll
                for (int j2 = 0; j2 < 9; j2++) acc[j2] = f2fma(vv, w2p[j2], acc[j2]);
                vv = pk(v3, v3);
#pragma unroll
                for (int j2 = 0; j2 < 9; j2++) acc[j2] = f2fma(vv, w3p[j2], acc[j2]);
            }
        }
    }
    float2* op = (float2*)(g_off + (size_t)p * 20);
#pragma unroll
    for (int j2 = 0; j2 < 9; j2++) {
        float lo, hi; upk(acc[j2], lo, hi);
        op[j2] = make_float2(lo, hi);
    }
}

// ---------------- Kernel 2: deformable conv ----------------
// Dynamic smem layout:
//   s_val : ull[128][66]  (dup-packed bilinear values, px-major)   67,584 B
//   W2s   : ull[64][32]   (oc-paired weights for current tap)      16,384 B
//   s_set : float[8][128] (bilinear setup)                          4,096 B
#define SVAL_PITCH 66
#define SMEM_W2S   67584
#define SMEM_SET   (67584 + 16384)
#define SMEM_TOTAL (SMEM_SET + 4096)

__global__ __launch_bounds__(256, 2) void k_deform(const float* __restrict__ bias,
                                                   float* __restrict__ out) {
    extern __shared__ __align__(16) char smem[];
    ull*   s_val = (ull*)smem;
    ull*   W2s   = (ull*)(smem + SMEM_W2S);
    float* s_set = (float*)(smem + SMEM_SET);   // [8][128] component-major

    int t  = threadIdx.x;
    int bx = blockIdx.x;
    int b  = bx >> 7, y = bx & 127;
    int pix0 = y << 7;

    const float* xb = g_xt + ((size_t)b << 20);
    int pxg = t >> 4;        // 16 groups of 8 px
    int ocg = t & 15;        // 16 groups of 4 oc

    ull acc[8][2];
    {
        ull b01 = pk(bias[ocg * 4 + 0], bias[ocg * 4 + 1]);
        ull b23 = pk(bias[ocg * 4 + 2], bias[ocg * 4 + 3]);
#pragma unroll
        for (int p = 0; p < 8; p++) { acc[p][0] = b01; acc[p][1] = b23; }
    }

    const float* offbase = g_off + (size_t)((b << 14) + pix0) * 20;

#pragma unroll 1
    for (int k = 0; k < KK; k++) {
        __syncthreads();
        // ---- stage A: bilinear setup + weight-tile fill ----
        if (t < 128) {
            float2 o = *(const float2*)(offbase + t * 20 + 2 * k);
            float py  = (float)(y + k / 3 - 1) + o.x;
            float pxf = (float)(t + k % 3 - 1) + o.y;
            float fy0 = floorf(py), fx0 = floorf(pxf);
            int y0 = (int)fy0, x0 = (int)fx0;
            int y1 = y0 + 1,   x1 = x0 + 1;
            float wy1 = py - fy0, wx1 = pxf - fx0;
            float wy0 = 1.f - wy1, wx0 = 1.f - wx1;
            bool vy0 = (unsigned)y0 < (unsigned)HH, vy1 = (unsigned)y1 < (unsigned)HH;
            bool vx0 = (unsigned)x0 < (unsigned)WW, vx1 = (unsigned)x1 < (unsigned)WW;
            s_set[0 * 128 + t] = (vy0 && vx0) ? wy0 * wx0 : 0.f;
            s_set[1 * 128 + t] = (vy0 && vx1) ? wy0 * wx1 : 0.f;
            s_set[2 * 128 + t] = (vy1 && vx0) ? wy1 * wx0 : 0.f;
            s_set[3 * 128 + t] = (vy1 && vx1) ? wy1 * wx1 : 0.f;
            int cy0 = min(max(y0, 0), HH - 1), cy1 = min(max(y1, 0), HH - 1);
            int cx0 = min(max(x0, 0), WW - 1), cx1 = min(max(x1, 0), WW - 1);
            s_set[4 * 128 + t] = __int_as_float(((cy0 << 7) + cx0) << 6);
            s_set[5 * 128 + t] = __int_as_float(((cy0 << 7) + cx1) << 6);
            s_set[6 * 128 + t] = __int_as_float(((cy1 << 7) + cx0) << 6);
            s_set[7 * 128 + t] = __int_as_float(((cy1 << 7) + cx1) << 6);
        }
        // fill oc-paired weight tile for this tap: W2s[c*32 + o2] = (w[2o2], w[2o2+1])
        {
            const float* wk = g_wt + k * (CH * OCH);
            for (int idx = t; idx < CH * 32; idx += 256) {
                int c = idx >> 5, o2 = idx & 31;
                float2 w = *(const float2*)(wk + c * 64 + o2 * 2);
                W2s[idx] = pk(w.x, w.y);
            }
        }
        __syncthreads();
        // ---- stage B: coalesced gather, scalar blend, dup-packed store ----
#pragma unroll
        for (int it = 0; it < 8; it++) {
            int slot = it * 256 + t;
            int pxl = slot >> 4, cg = slot & 15;
            float w00 = s_set[0 * 128 + pxl], w01 = s_set[1 * 128 + pxl];
            float w10 = s_set[2 * 128 + pxl], w11 = s_set[3 * 128 + pxl];
            int i00 = __float_as_int(s_set[4 * 128 + pxl]);
            int i01 = __float_as_int(s_set[5 * 128 + pxl]);
            int i10 = __float_as_int(s_set[6 * 128 + pxl]);
            int i11 = __float_as_int(s_set[7 * 128 + pxl]);
            float4 A = *((const float4*)(xb + i00) + cg);
            float4 Bq = *((const float4*)(xb + i01) + cg);
            float4 Cq = *((const float4*)(xb + i10) + cg);
            float4 D = *((const float4*)(xb + i11) + cg);
            float v0 = fmaf(w11, D.x, fmaf(w10, Cq.x, fmaf(w01, Bq.x, w00 * A.x)));
            float v1 = fmaf(w11, D.y, fmaf(w10, Cq.y, fmaf(w01, Bq.y, w00 * A.y)));
            float v2 = fmaf(w11, D.z, fmaf(w10, Cq.z, fmaf(w01, Bq.z, w00 * A.z)));
            float v3 = fmaf(w11, D.w, fmaf(w10, Cq.w, fmaf(w01, Bq.w, w00 * A.w)));
            ull* dst = s_val + pxl * SVAL_PITCH + cg * 4;
            ulonglong2 q0, q1;
            q0.x = pk(v0, v0); q0.y = pk(v1, v1);
            q1.x = pk(v2, v2); q1.y = pk(v3, v3);
            *(ulonglong2*)dst = q0;
            *(ulonglong2*)(dst + 2) = q1;
        }
        __syncthreads();
        // ---- stage C: pure-FFMA2 rank update (8 px x 4 oc per thread) ----
        const ull* vb = s_val + pxg * 8 * SVAL_PITCH;
        const ull* wb = W2s + ocg * 2;
#pragma unroll 2
        for (int cp = 0; cp < 32; cp++) {
            ulonglong2 wq0 = *(const ulonglong2*)(wb + (2 * cp) * 32);
            ulonglong2 wq1 = *(const ulonglong2*)(wb + (2 * cp + 1) * 32);
#pragma unroll
            for (int p = 0; p < 8; p++) {
                ulonglong2 vv = *(const ulonglong2*)(vb + p * SVAL_PITCH + 2 * cp);
                acc[p][0] = f2fma(vv.x, wq0.x, acc[p][0]);
                acc[p][1] = f2fma(vv.x, wq0.y, acc[p][1]);
                acc[p][0] = f2fma(vv.y, wq1.x, acc[p][0]);
                acc[p][1] = f2fma(vv.y, wq1.y, acc[p][1]);
            }
        }
    }

    // ---- epilogue: transpose through smem, coalesced NCHW stores ----
    __syncthreads();
    float* sp = (float*)smem;   // reuse s_val region: [oc][px] pitch 133
#pragma unroll
    for (int p = 0; p < 8; p++) {
        int px = pxg * 8 + p;
        float o0, o1, o2, o3;
        upk(acc[p][0], o0, o1);
        upk(acc[p][1], o2, o3);
        sp[(ocg * 4 + 0) * 133 + px] = o0;
        sp[(ocg * 4 + 1) * 133 + px] = o1;
        sp[(ocg * 4 + 2) * 133 + px] = o2;
        sp[(ocg * 4 + 3) * 133 + px] = o3;
    }
    __syncthreads();
    float* ob = out + (((size_t)b << 6) << 14) + pix0;
#pragma unroll
    for (int it = 0; it < 32; it++) {
        int idx = it * 256 + t;
        int oc = idx >> 7, px = idx & 127;
        ob[((size_t)oc << 14) + px] = sp[oc * 133 + px];
    }
}

extern "C" void kernel_launch(void* const* d_in, const int* in_sizes, int n_in,
                              void* d_out, int out_size) {
    const float* x      = (const float*)d_in[0];
    const float* offw   = (const float*)d_in[1];
    const float* offb   = (const float*)d_in[2];
    const float* weight = (const float*)d_in[3];
    const float* bias   = (const float*)d_in[4];
    float* out = (float*)d_out;

    cudaFuncSetAttribute(k_deform, cudaFuncAttributeMaxDynamicSharedMemorySize,
                         SMEM_TOTAL);

    k_transpose<<<2048, 256>>>(x);
    k_wtrans<<<(KK * CH * OCH + 255) / 256, 256>>>(weight);
    k_offset<<<NPIX / 128, 128>>>(x, offw, offb);
    k_deform<<<512, 256, SMEM_TOTAL>>>(bias, out);
}

// round 7
// speedup vs baseline: 3.5431x; 1.6667x over previous
#include <cuda_runtime.h>
#include <cuda_bf16.h>
#include <cstdint>

// B=4, C=64, H=W=128, O=64, K=3, pad=1, stride=1
#define BATCH 4
#define CH    64
#define HH    128
#define WW    128
#define HW    16384
#define NPIX  65536
#define OCH   64
#define KK    9

// Scratch (__device__ globals; no cudaMalloc allowed)
__device__ __align__(16) float g_xt[BATCH * HW * CH];            // NHWC x, 16 MB
__device__ __align__(16) float g_off[NPIX * 20];                 // pixel-major offsets
__device__ __align__(16) __nv_bfloat16 g_wbh[KK * OCH * CH];     // weight hi [k][oc][c]
__device__ __align__(16) __nv_bfloat16 g_wbl[KK * OCH * CH];     // weight lo [k][oc][c]

typedef unsigned long long ull;

static __device__ __forceinline__ unsigned smem_u32(const void* p) {
    unsigned a;
    asm("{ .reg .u64 t; cvta.to.shared.u64 t, %1; cvt.u32.u64 %0, t; }" : "=r"(a) : "l"(p));
    return a;
}
// ldmatrix x4 (non-transposed), b16
static __device__ __forceinline__ void ldsm4(unsigned* r, unsigned addr) {
    asm volatile("ldmatrix.sync.aligned.m8n8.x4.shared.b16 {%0,%1,%2,%3}, [%4];"
        : "=r"(r[0]), "=r"(r[1]), "=r"(r[2]), "=r"(r[3]) : "r"(addr));
}
// mma m16n8k16 row.col f32 <- bf16*bf16 + f32
static __device__ __forceinline__ void mma_bf16(float* d, const unsigned* a,
                                                unsigned b0, unsigned b1) {
    asm volatile("mma.sync.aligned.m16n8k16.row.col.f32.bf16.bf16.f32 "
        "{%0,%1,%2,%3}, {%4,%5,%6,%7}, {%8,%9}, {%0,%1,%2,%3};"
        : "+f"(d[0]), "+f"(d[1]), "+f"(d[2]), "+f"(d[3])
        : "r"(a[0]), "r"(a[1]), "r"(a[2]), "r"(a[3]), "r"(b0), "r"(b1));
}

// ---------------- f32x2 helpers (k_offset) ----------------
static __device__ __forceinline__ ull pk(float lo, float hi) {
    ull r;
    asm("mov.b64 %0, {%1, %2};" : "=l"(r)
        : "r"(__float_as_uint(lo)), "r"(__float_as_uint(hi)));
    return r;
}
static __device__ __forceinline__ void upk(ull v, float& lo, float& hi) {
    unsigned a, b;
    asm("mov.b64 {%0, %1}, %2;" : "=r"(a), "=r"(b) : "l"(v));
    lo = __uint_as_float(a); hi = __uint_as_float(b);
}
static __device__ __forceinline__ ull f2fma(ull a, ull b, ull c) {
    ull d;
    asm("fma.rn.f32x2 %0, %1, %2, %3;" : "=l"(d) : "l"(a), "l"(b), "l"(c));
    return d;
}

// ---------------- Kernel 0: NCHW -> NHWC transpose of x ----------------
__global__ void k_transpose(const float* __restrict__ x) {
    __shared__ float tile[8][33];
    int bid = blockIdx.x;
    int b  = bid >> 9;
    int p0 = (bid & 511) << 5;
    int tx = threadIdx.x & 31, ty = threadIdx.x >> 5;
    int cx = threadIdx.x & 7,  pw = threadIdx.x >> 3;
    for (int c0 = 0; c0 < CH; c0 += 8) {
        tile[ty][tx] = x[(((size_t)(b * CH + c0 + ty)) << 14) + p0 + tx];
        __syncthreads();
        g_xt[(((size_t)((b << 14) + p0 + pw)) << 6) + c0 + cx] = tile[cx][pw];
        __syncthreads();
    }
}

// ---------------- Kernel 0b: weight split -> bf16 hi/lo, [k][oc][c] ----------------
__global__ void k_wsplit(const float* __restrict__ w) {
    int i = blockIdx.x * 256 + threadIdx.x;
    if (i < KK * OCH * CH) {
        int k = i / (OCH * CH), r = i % (OCH * CH);
        int oc = r >> 6, c = r & 63;
        float v = w[(oc * CH + c) * KK + k];
        __nv_bfloat16 h = __float2bfloat16(v);
        float rest = v - __bfloat162float(h);
        g_wbh[i] = h;
        g_wbl[i] = __float2bfloat16(rest);
    }
}

// ---------------- Kernel 1: offset conv (3x3, 64->18), reads NCHW x ----------------
__global__ __launch_bounds__(128) void k_offset(const float* __restrict__ x,
                                                const float* __restrict__ offw,
                                                const float* __restrict__ offb) {
    __shared__ __align__(16) ull ws2[KK * CH * 9];
    for (int idx = threadIdx.x; idx < KK * CH * 9; idx += 128) {
        int k = idx / 576, r = idx % 576, c = r / 9, j2 = r % 9;
        float w0 = offw[((2 * j2) * CH + c) * 9 + k];
        float w1 = offw[((2 * j2 + 1) * CH + c) * 9 + k];
        ws2[idx] = pk(w0, w1);
    }
    __syncthreads();

    int p   = blockIdx.x * 128 + threadIdx.x;
    int b   = p >> 14, pix = p & 16383;
    int y   = pix >> 7, xx = pix & 127;

    ull acc[9];
#pragma unroll
    for (int j2 = 0; j2 < 9; j2++) acc[j2] = pk(offb[2 * j2], offb[2 * j2 + 1]);

    const float* xb = x + ((size_t)b << 20);

#pragma unroll 1
    for (int k = 0; k < KK; k++) {
        int iy = y + k / 3 - 1, ix = xx + k % 3 - 1;
        if ((unsigned)iy < (unsigned)HH && (unsigned)ix < (unsigned)WW) {
            const float* src = xb + (iy << 7) + ix;
            const ull* wk = ws2 + k * 576;
#pragma unroll 4
            for (int c4 = 0; c4 < 16; c4++) {
                float v0 = src[(size_t)(c4 * 4 + 0) << 14];
                float v1 = src[(size_t)(c4 * 4 + 1) << 14];
                float v2 = src[(size_t)(c4 * 4 + 2) << 14];
                float v3 = src[(size_t)(c4 * 4 + 3) << 14];
                const ull* w0p = wk + (c4 * 4 + 0) * 9;
                const ull* w1p = wk + (c4 * 4 + 1) * 9;
                const ull* w2p = wk + (c4 * 4 + 2) * 9;
                const ull* w3p = wk + (c4 * 4 + 3) * 9;
                ull vv;
                vv = pk(v0, v0);
#pragma unroll
                for (int j2 = 0; j2 < 9; j2++) acc[j2] = f2fma(vv, w0p[j2], acc[j2]);
                vv = pk(v1, v1);
#pragma unroll
                for (int j2 = 0; j2 < 9; j2++) acc[j2] = f2fma(vv, w1p[j2], acc[j2]);
                vv = pk(v2, v2);
#pragma unroll
                for (int j2 = 0; j2 < 9; j2++) acc[j2] = f2fma(vv, w2p[j2], acc[j2]);
                vv = pk(v3, v3);
#pragma unroll
                for (int j2 = 0; j2 < 9; j2++) acc[j2] = f2fma(vv, w3p[j2], acc[j2]);
            }
        }
    }
    float2* op = (float2*)(g_off + (size_t)p * 20);
#pragma unroll
    for (int j2 = 0; j2 < 9; j2++) {
        float lo, hi; upk(acc[j2], lo, hi);
        op[j2] = make_float2(lo, hi);
    }
}

// ---------------- Kernel 2: deformable conv via mma.sync split-bf16 ----------------
// Block = one image row: D[128px, 64oc] += sum over 9 taps of V[128,64]·W[64,64]^T.
// 4 warps, each 32px x 64oc, fp32 accumulators in registers (HMMA).
// Swizzle: 16B chunk c stored at c ^ (row & 7) within the 128B row.
#define SM_AH   0
#define SM_AL   16384
#define SM_BH   32768
#define SM_BL   40960
#define SM_SET  49152
#define SMEM_TOTAL 53248

__global__ __launch_bounds__(128, 4) void k_deform(const float* __restrict__ bias,
                                                   float* __restrict__ out) {
    extern __shared__ __align__(1024) char smem[];
    unsigned sb = smem_u32(smem);
    float* s_set = (float*)(smem + SM_SET);

    int t = threadIdx.x, l = t & 31, w = t >> 5;
    int bx = blockIdx.x;
    int b  = bx >> 7, y = bx & 127;
    int pix0 = y << 7;

    const float* xb = g_xt + ((size_t)b << 20);
    const float* offbase = g_off + (size_t)((b << 14) + pix0) * 20;

    float acc[2][8][4];
#pragma unroll
    for (int mi = 0; mi < 2; mi++)
#pragma unroll
        for (int ni = 0; ni < 8; ni++)
#pragma unroll
            for (int j = 0; j < 4; j++) acc[mi][ni][j] = 0.f;

    // lane-constant ldmatrix addressing
    int arow  = (l & 7) | (l & 8);     // A: tile row within 16
    int axor  = (l & 7);               // swizzle xor for both A and B lanes
    int ahalf = (l >> 4) & 1;          // A k-chunk half select
    int brow  = (((l >> 4) & 1) << 3) | (l & 7);  // B row offset within 16-oc pair
    int bhalf = (l >> 3) & 1;

#pragma unroll 1
    for (int k = 0; k < KK; k++) {
        __syncthreads();
        // ---- bilinear setup (thread = pixel) ----
        {
            float2 o = *(const float2*)(offbase + t * 20 + 2 * k);
            float py  = (float)(y + k / 3 - 1) + o.x;
            float pxf = (float)(t + k % 3 - 1) + o.y;
            float fy0 = floorf(py), fx0 = floorf(pxf);
            int y0 = (int)fy0, x0 = (int)fx0;
            int y1 = y0 + 1,   x1 = x0 + 1;
            float wy1 = py - fy0, wx1 = pxf - fx0;
            float wy0 = 1.f - wy1, wx0 = 1.f - wx1;
            bool vy0 = (unsigned)y0 < (unsigned)HH, vy1 = (unsigned)y1 < (unsigned)HH;
            bool vx0 = (unsigned)x0 < (unsigned)WW, vx1 = (unsigned)x1 < (unsigned)WW;
            s_set[0 * 128 + t] = (vy0 && vx0) ? wy0 * wx0 : 0.f;
            s_set[1 * 128 + t] = (vy0 && vx1) ? wy0 * wx1 : 0.f;
            s_set[2 * 128 + t] = (vy1 && vx0) ? wy1 * wx0 : 0.f;
            s_set[3 * 128 + t] = (vy1 && vx1) ? wy1 * wx1 : 0.f;
            int cy0 = min(max(y0, 0), HH - 1), cy1 = min(max(y1, 0), HH - 1);
            int cx0 = min(max(x0, 0), WW - 1), cx1 = min(max(x1, 0), WW - 1);
            s_set[4 * 128 + t] = __int_as_float(((cy0 << 7) + cx0) << 6);
            s_set[5 * 128 + t] = __int_as_float(((cy0 << 7) + cx1) << 6);
            s_set[6 * 128 + t] = __int_as_float(((cy1 << 7) + cx0) << 6);
            s_set[7 * 128 + t] = __int_as_float(((cy1 << 7) + cx1) << 6);
        }
        // ---- B tiles: 8KB hi + 8KB lo, swizzled ----
        {
            const uint4* srcH = (const uint4*)(g_wbh + k * (OCH * CH));
            const uint4* srcL = (const uint4*)(g_wbl + k * (OCH * CH));
#pragma unroll
            for (int it = 0; it < 4; it++) {
                int idx = it * 128 + t;
                int row = idx >> 3, ch = idx & 7;
                int dst = row * 128 + ((ch ^ (row & 7)) << 4);
                *(uint4*)(smem + SM_BH + dst) = srcH[idx];
                *(uint4*)(smem + SM_BL + dst) = srcL[idx];
            }
        }
        __syncthreads();
        // ---- gather + blend + bf16 split into swizzled A tiles ----
#pragma unroll
        for (int it = 0; it < 8; it++) {
            int slot = it * 128 + t;
            int pxl = slot >> 3, cg = slot & 7;
            float w00 = s_set[0 * 128 + pxl], w01 = s_set[1 * 128 + pxl];
            float w10 = s_set[2 * 128 + pxl], w11 = s_set[3 * 128 + pxl];
            int i00 = __float_as_int(s_set[4 * 128 + pxl]);
            int i01 = __float_as_int(s_set[5 * 128 + pxl]);
            int i10 = __float_as_int(s_set[6 * 128 + pxl]);
            int i11 = __float_as_int(s_set[7 * 128 + pxl]);
            const float4* q00 = (const float4*)(xb + i00) + cg * 2;
            const float4* q01 = (const float4*)(xb + i01) + cg * 2;
            const float4* q10 = (const float4*)(xb + i10) + cg * 2;
            const float4* q11 = (const float4*)(xb + i11) + cg * 2;
            float vv[8];
#pragma unroll
            for (int hcg = 0; hcg < 2; hcg++) {
                float4 A = q00[hcg], Bq = q01[hcg], Cq = q10[hcg], D = q11[hcg];
                vv[hcg*4+0] = fmaf(w11, D.x, fmaf(w10, Cq.x, fmaf(w01, Bq.x, w00 * A.x)));
                vv[hcg*4+1] = fmaf(w11, D.y, fmaf(w10, Cq.y, fmaf(w01, Bq.y, w00 * A.y)));
                vv[hcg*4+2] = fmaf(w11, D.z, fmaf(w10, Cq.z, fmaf(w01, Bq.z, w00 * A.z)));
                vv[hcg*4+3] = fmaf(w11, D.w, fmaf(w10, Cq.w, fmaf(w01, Bq.w, w00 * A.w)));
            }
            uint4 hq, lq;
            unsigned* hp = (unsigned*)&hq;
            unsigned* lp = (unsigned*)&lq;
#pragma unroll
            for (int j = 0; j < 4; j++) {
                __nv_bfloat162 h = __floats2bfloat162_rn(vv[2*j], vv[2*j+1]);
                float r0 = vv[2*j]   - __bfloat162float(__low2bfloat16(h));
                float r1 = vv[2*j+1] - __bfloat162float(__high2bfloat16(h));
                __nv_bfloat162 lo2 = __floats2bfloat162_rn(r0, r1);
                hp[j] = *(unsigned*)&h;
                lp[j] = *(unsigned*)&lo2;
            }
            int dst = pxl * 128 + ((cg ^ (pxl & 7)) << 4);
            *(uint4*)(smem + SM_AH + dst) = hq;
            *(uint4*)(smem + SM_AL + dst) = lq;
        }
        __syncthreads();
        // ---- tensor-core passes: AhBh + AhBl + AlBh, K=64 (4 ksteps) ----
#pragma unroll
        for (int ks = 0; ks < 4; ks++) {
            unsigned ah[2][4], al[2][4];
#pragma unroll
            for (int mi = 0; mi < 2; mi++) {
                int row = w * 32 + mi * 16 + arow;
                unsigned ad = sb + SM_AH + row * 128 + ((((ks << 1) + ahalf) ^ axor) << 4);
                ldsm4(ah[mi], ad);
                ldsm4(al[mi], ad + (SM_AL - SM_AH));
            }
#pragma unroll
            for (int np = 0; np < 4; np++) {
                int rowb = np * 16 + brow;
                unsigned bd = sb + SM_BH + rowb * 128 + ((((ks << 1) + bhalf) ^ axor) << 4);
                unsigned bh[4], bl[4];
                ldsm4(bh, bd);
                ldsm4(bl, bd + (SM_BL - SM_BH));
#pragma unroll
                for (int mi = 0; mi < 2; mi++) {
#pragma unroll
                    for (int nt = 0; nt < 2; nt++) {
                        float* d = acc[mi][np * 2 + nt];
                        mma_bf16(d, ah[mi], bh[2 * nt], bh[2 * nt + 1]);
                        mma_bf16(d, ah[mi], bl[2 * nt], bl[2 * nt + 1]);
                        mma_bf16(d, al[mi], bh[2 * nt], bh[2 * nt + 1]);
                    }
                }
            }
        }
    }

    // ---- epilogue: regs -> smem [oc][px] -> coalesced NCHW stores ----
    __syncthreads();
    float* sp = (float*)smem;   // pitch 132 floats
#pragma unroll
    for (int mi = 0; mi < 2; mi++)
#pragma unroll
        for (int ni = 0; ni < 8; ni++) {
            int row = w * 32 + mi * 16 + (l >> 2);
            int col = ni * 8 + (l & 3) * 2;
            float b0 = bias[col], b1 = bias[col + 1];
            sp[col * 132 + row]           = acc[mi][ni][0] + b0;
            sp[(col + 1) * 132 + row]     = acc[mi][ni][1] + b1;
            sp[col * 132 + row + 8]       = acc[mi][ni][2] + b0;
            sp[(col + 1) * 132 + row + 8] = acc[mi][ni][3] + b1;
        }
    __syncthreads();
    float* ob = out + (((size_t)b << 6) << 14) + pix0;
#pragma unroll
    for (int it = 0; it < 64; it++) {
        int i = it * 128 + t;
        int oc = i >> 7, px = i & 127;
        ob[((size_t)oc << 14) + px] = sp[oc * 132 + px];
    }
}

extern "C" void kernel_launch(void* const* d_in, const int* in_sizes, int n_in,
                              void* d_out, int out_size) {
    const float* x      = (const float*)d_in[0];
    const float* offw   = (const float*)d_in[1];
    const float* offb   = (const float*)d_in[2];
    const float* weight = (const float*)d_in[3];
    const float* bias   = (const float*)d_in[4];
    float* out = (float*)d_out;

    cudaFuncSetAttribute(k_deform, cudaFuncAttributeMaxDynamicSharedMemorySize,
                         SMEM_TOTAL);

    k_transpose<<<2048, 256>>>(x);
    k_wsplit<<<(KK * OCH * CH + 255) / 256, 256>>>(weight);
    k_offset<<<NPIX / 128, 128>>>(x, offw, offb);
    k_deform<<<512, 128, SMEM_TOTAL>>>(bias, out);
}

// round 8
// speedup vs baseline: 4.6047x; 1.2996x over previous
#include <cuda_runtime.h>
#include <cuda_bf16.h>
#include <cstdint>

// B=4, C=64, H=W=128, O=64, K=3, pad=1, stride=1
#define BATCH 4
#define CH    64
#define HH    128
#define WW    128
#define HW    16384
#define NPIX  65536
#define OCH   64
#define KK    9

// Scratch (__device__ globals; no cudaMalloc allowed)
__device__ __align__(16) float g_xt[BATCH * HW * CH];            // NHWC x, 16 MB
__device__ __align__(16) float g_off[NPIX * 20];                 // pixel-major offsets
__device__ __align__(16) __nv_bfloat16 g_wbh[KK * OCH * CH];     // deform weight hi [k][oc][c]
__device__ __align__(16) __nv_bfloat16 g_wbl[KK * OCH * CH];     // deform weight lo
__device__ __align__(16) __nv_bfloat16 g_owbh[KK * 32 * CH];     // offset weight hi [k][j(32)][c]
__device__ __align__(16) __nv_bfloat16 g_owbl[KK * 32 * CH];     // offset weight lo

static __device__ __forceinline__ unsigned smem_u32(const void* p) {
    unsigned a;
    asm("{ .reg .u64 t; cvta.to.shared.u64 t, %1; cvt.u32.u64 %0, t; }" : "=r"(a) : "l"(p));
    return a;
}
static __device__ __forceinline__ void ldsm4(unsigned* r, unsigned addr) {
    asm volatile("ldmatrix.sync.aligned.m8n8.x4.shared.b16 {%0,%1,%2,%3}, [%4];"
        : "=r"(r[0]), "=r"(r[1]), "=r"(r[2]), "=r"(r[3]) : "r"(addr));
}
static __device__ __forceinline__ void mma_bf16(float* d, const unsigned* a,
                                                unsigned b0, unsigned b1) {
    asm volatile("mma.sync.aligned.m16n8k16.row.col.f32.bf16.bf16.f32 "
        "{%0,%1,%2,%3}, {%4,%5,%6,%7}, {%8,%9}, {%0,%1,%2,%3};"
        : "+f"(d[0]), "+f"(d[1]), "+f"(d[2]), "+f"(d[3])
        : "r"(a[0]), "r"(a[1]), "r"(a[2]), "r"(a[3]), "r"(b0), "r"(b1));
}
static __device__ __forceinline__ void split8(const float4& a, const float4& b,
                                              uint4& hq, uint4& lq) {
    float vv[8] = {a.x, a.y, a.z, a.w, b.x, b.y, b.z, b.w};
    unsigned* hp = (unsigned*)&hq;
    unsigned* lp = (unsigned*)&lq;
#pragma unroll
    for (int j = 0; j < 4; j++) {
        __nv_bfloat162 h = __floats2bfloat162_rn(vv[2*j], vv[2*j+1]);
        float r0 = vv[2*j]   - __bfloat162float(__low2bfloat16(h));
        float r1 = vv[2*j+1] - __bfloat162float(__high2bfloat16(h));
        __nv_bfloat162 lo2 = __floats2bfloat162_rn(r0, r1);
        hp[j] = *(unsigned*)&h;
        lp[j] = *(unsigned*)&lo2;
    }
}

// ---------------- Kernel 0: NCHW -> NHWC transpose of x ----------------
__global__ void k_transpose(const float* __restrict__ x) {
    __shared__ float tile[8][33];
    int bid = blockIdx.x;
    int b  = bid >> 9;
    int p0 = (bid & 511) << 5;
    int tx = threadIdx.x & 31, ty = threadIdx.x >> 5;
    int cx = threadIdx.x & 7,  pw = threadIdx.x >> 3;
    for (int c0 = 0; c0 < CH; c0 += 8) {
        tile[ty][tx] = x[(((size_t)(b * CH + c0 + ty)) << 14) + p0 + tx];
        __syncthreads();
        g_xt[(((size_t)((b << 14) + p0 + pw)) << 6) + c0 + cx] = tile[cx][pw];
        __syncthreads();
    }
}

// ---------------- Kernel 0b: deform weight split -> bf16 hi/lo, [k][oc][c] ----------------
__global__ void k_wsplit(const float* __restrict__ w) {
    int i = blockIdx.x * 256 + threadIdx.x;
    if (i < KK * OCH * CH) {
        int k = i / (OCH * CH), r = i % (OCH * CH);
        int oc = r >> 6, c = r & 63;
        float v = w[(oc * CH + c) * KK + k];
        __nv_bfloat16 h = __float2bfloat16(v);
        g_wbh[i] = h;
        g_wbl[i] = __float2bfloat16(v - __bfloat162float(h));
    }
}
// offset weight split -> [k][j<32 pad][c]
__global__ void k_owsplit(const float* __restrict__ ow) {
    int i = blockIdx.x * 256 + threadIdx.x;
    if (i < KK * 32 * CH) {
        int k = i / (32 * CH), r = i % (32 * CH);
        int j = r >> 6, c = r & 63;
        float v = (j < 18) ? ow[(j * CH + c) * 9 + k] : 0.f;
        __nv_bfloat16 h = __float2bfloat16(v);
        g_owbh[i] = h;
        g_owbl[i] = __float2bfloat16(v - __bfloat162float(h));
    }
}

// ---------------- Kernel 1: offset conv via HMMA split-bf16 ----------------
// Block = one image row. A tile = one input row (130 px halo'd, 64 ch) split bf16,
// shared by the 3 horizontal taps via ldmatrix address shift (+-128B per px).
// D[128px, 32(18 used)] in register accumulators.
#define OS_AH 0
#define OS_AL 16640
#define OS_BH 33280
#define OS_BL 37376
#define OS_TOT 41472

__global__ __launch_bounds__(128, 4) void k_offmma(const float* __restrict__ offb) {
    __shared__ __align__(128) char smem2[OS_TOT];
    unsigned sb = smem_u32(smem2);

    int t = threadIdx.x, l = t & 31, w = t >> 5;
    int bx = blockIdx.x;
    int b  = bx >> 7, y = bx & 127;
    int pix0 = y << 7;

    float acc[2][4][4];
#pragma unroll
    for (int mi = 0; mi < 2; mi++)
#pragma unroll
        for (int ni = 0; ni < 4; ni++)
#pragma unroll
            for (int j = 0; j < 4; j++) acc[mi][ni][j] = 0.f;

    int arow  = (l & 7) | (l & 8);
    int ahalf = (l >> 4) & 1;
    int brow  = (((l >> 4) & 1) << 3) | (l & 7);
    int bhalf = (l >> 3) & 1;

    // zero halo rows (tile rows 0 and 129) of both A tiles
    if (t < 32) {
        int tile = t >> 4;             // 0 = hi, 1 = lo
        int rr   = ((t >> 3) & 1) ? 129 : 0;
        int ch   = t & 7;
        *(uint4*)(smem2 + (tile ? OS_AL : OS_AH) + rr * 128 + ch * 16) =
            make_uint4(0, 0, 0, 0);
    }

#pragma unroll 1
    for (int dyi = 0; dyi < 3; dyi++) {
        int row = y + dyi - 1;
        if ((unsigned)row >= (unsigned)HH) continue;
        __syncthreads();   // prior taps done reading A
        // ---- fill A rows 1..128 from g_xt[b][row] ----
        const float4* src = (const float4*)g_xt +
                            (((size_t)((b << 14) + (row << 7))) << 4);
#pragma unroll
        for (int it = 0; it < 8; it++) {
            int idx = it * 128 + t;
            int pxl = idx >> 3, ch = idx & 7;
            const float4* s4 = src + pxl * 16 + ch * 2;
            float4 a = s4[0], bq = s4[1];
            uint4 hq, lq;
            split8(a, bq, hq, lq);
            int r1 = pxl + 1;
            int dst = r1 * 128 + ((ch ^ (r1 & 7)) << 4);
            *(uint4*)(smem2 + OS_AH + dst) = hq;
            *(uint4*)(smem2 + OS_AL + dst) = lq;
        }
#pragma unroll 1
        for (int dxi = 0; dxi < 3; dxi++) {
            int k = dyi * 3 + dxi;
            __syncthreads();   // A ready / prior B done
            // ---- fill B tap tile (32 x 64, hi+lo) ----
            {
                const uint4* bh4 = (const uint4*)(g_owbh + k * (32 * CH));
                const uint4* bl4 = (const uint4*)(g_owbl + k * (32 * CH));
#pragma unroll
                for (int u0 = 0; u0 < 2; u0++) {
                    int u = u0 * 128 + t;
                    int rowb = u >> 3, ch = u & 7;
                    int dst = rowb * 128 + ((ch ^ (rowb & 7)) << 4);
                    *(uint4*)(smem2 + OS_BH + dst) = bh4[u];
                    *(uint4*)(smem2 + OS_BL + dst) = bl4[u];
                }
            }
            __syncthreads();
            // ---- MMA: AhBh + AhBl + AlBh over K=64 ----
#pragma unroll
            for (int ks = 0; ks < 4; ks++) {
                unsigned ah[2][4], al[2][4];
#pragma unroll
                for (int mi = 0; mi < 2; mi++) {
                    int tr = w * 32 + mi * 16 + arow + dxi;   // pixel + dx + 1
                    unsigned ad = sb + OS_AH + tr * 128 +
                                  ((((ks << 1) + ahalf) ^ (tr & 7)) << 4);
                    ldsm4(ah[mi], ad);
                    ldsm4(al[mi], ad + (OS_AL - OS_AH));
                }
#pragma unroll
                for (int np = 0; np < 2; np++) {
                    int rowb = np * 16 + brow;
                    unsigned bd = sb + OS_BH + rowb * 128 +
                                  ((((ks << 1) + bhalf) ^ (rowb & 7)) << 4);
                    unsigned bh[4], bl[4];
                    ldsm4(bh, bd);
                    ldsm4(bl, bd + (OS_BL - OS_BH));
#pragma unroll
                    for (int mi = 0; mi < 2; mi++) {
#pragma unroll
                        for (int nt = 0; nt < 2; nt++) {
                            float* d = acc[mi][np * 2 + nt];
                            mma_bf16(d, ah[mi], bh[2 * nt], bh[2 * nt + 1]);
                            mma_bf16(d, ah[mi], bl[2 * nt], bl[2 * nt + 1]);
                            mma_bf16(d, al[mi], bh[2 * nt], bh[2 * nt + 1]);
                        }
                    }
                }
            }
        }
    }

    // ---- epilogue: regs -> smem stage [128px][20] -> g_off ----
    __syncthreads();
    float* st = (float*)smem2;
#pragma unroll
    for (int mi = 0; mi < 2; mi++)
#pragma unroll
        for (int ni = 0; ni < 3; ni++) {       // n-tiles 0..2 cover cols 0..23
            int row0 = w * 32 + mi * 16 + (l >> 2);
            int col  = ni * 8 + (l & 3) * 2;
            if (col < 18) {
                float b0 = offb[col], b1 = offb[col + 1];
                st[row0 * 20 + col]           = acc[mi][ni][0] + b0;
                st[row0 * 20 + col + 1]       = acc[mi][ni][1] + b1;
                st[(row0 + 8) * 20 + col]     = acc[mi][ni][2] + b0;
                st[(row0 + 8) * 20 + col + 1] = acc[mi][ni][3] + b1;
            }
        }
    __syncthreads();
    float4* dst = (float4*)(g_off + (size_t)((b << 14) + pix0) * 20);
    const float4* s4 = (const float4*)st;
#pragma unroll
    for (int it = 0; it < 5; it++)
        dst[it * 128 + t] = s4[it * 128 + t];
}

// ---------------- Kernel 2: deformable conv via mma.sync split-bf16 ----------------
#define SM_AH   0
#define SM_AL   16384
#define SM_BH   32768
#define SM_BL   40960
#define SM_SET  49152
#define SMEM_TOTAL 53248

__global__ __launch_bounds__(128, 4) void k_deform(const float* __restrict__ bias,
                                                   float* __restrict__ out) {
    extern __shared__ __align__(1024) char smem[];
    unsigned sb = smem_u32(smem);
    float* s_set = (float*)(smem + SM_SET);

    int t = threadIdx.x, l = t & 31, w = t >> 5;
    int bx = blockIdx.x;
    int b  = bx >> 7, y = bx & 127;
    int pix0 = y << 7;

    const float* xb = g_xt + ((size_t)b << 20);
    const float* offbase = g_off + (size_t)((b << 14) + pix0) * 20;

    float acc[2][8][4];
#pragma unroll
    for (int mi = 0; mi < 2; mi++)
#pragma unroll
        for (int ni = 0; ni < 8; ni++)
#pragma unroll
            for (int j = 0; j < 4; j++) acc[mi][ni][j] = 0.f;

    int arow  = (l & 7) | (l & 8);
    int axor  = (l & 7);
    int ahalf = (l >> 4) & 1;
    int brow  = (((l >> 4) & 1) << 3) | (l & 7);
    int bhalf = (l >> 3) & 1;

#pragma unroll 1
    for (int k = 0; k < KK; k++) {
        __syncthreads();
        {
            float2 o = *(const float2*)(offbase + t * 20 + 2 * k);
            float py  = (float)(y + k / 3 - 1) + o.x;
            float pxf = (float)(t + k % 3 - 1) + o.y;
            float fy0 = floorf(py), fx0 = floorf(pxf);
            int y0 = (int)fy0, x0 = (int)fx0;
            int y1 = y0 + 1,   x1 = x0 + 1;
            float wy1 = py - fy0, wx1 = pxf - fx0;
            float wy0 = 1.f - wy1, wx0 = 1.f - wx1;
            bool vy0 = (unsigned)y0 < (unsigned)HH, vy1 = (unsigned)y1 < (unsigned)HH;
            bool vx0 = (unsigned)x0 < (unsigned)WW, vx1 = (unsigned)x1 < (unsigned)WW;
            s_set[0 * 128 + t] = (vy0 && vx0) ? wy0 * wx0 : 0.f;
            s_set[1 * 128 + t] = (vy0 && vx1) ? wy0 * wx1 : 0.f;
            s_set[2 * 128 + t] = (vy1 && vx0) ? wy1 * wx0 : 0.f;
            s_set[3 * 128 + t] = (vy1 && vx1) ? wy1 * wx1 : 0.f;
            int cy0 = min(max(y0, 0), HH - 1), cy1 = min(max(y1, 0), HH - 1);
            int cx0 = min(max(x0, 0), WW - 1), cx1 = min(max(x1, 0), WW - 1);
            s_set[4 * 128 + t] = __int_as_float(((cy0 << 7) + cx0) << 6);
            s_set[5 * 128 + t] = __int_as_float(((cy0 << 7) + cx1) << 6);
            s_set[6 * 128 + t] = __int_as_float(((cy1 << 7) + cx0) << 6);
            s_set[7 * 128 + t] = __int_as_float(((cy1 << 7) + cx1) << 6);
        }
        {
            const uint4* srcH = (const uint4*)(g_wbh + k * (OCH * CH));
            const uint4* srcL = (const uint4*)(g_wbl + k * (OCH * CH));
#pragma unroll
            for (int it = 0; it < 4; it++) {
                int idx = it * 128 + t;
                int row = idx >> 3, ch = idx & 7;
                int dst = row * 128 + ((ch ^ (row & 7)) << 4);
                *(uint4*)(smem + SM_BH + dst) = srcH[idx];
                *(uint4*)(smem + SM_BL + dst) = srcL[idx];
            }
        }
        __syncthreads();
#pragma unroll
        for (int it = 0; it < 8; it++) {
            int slot = it * 128 + t;
            int pxl = slot >> 3, cg = slot & 7;
            float w00 = s_set[0 * 128 + pxl], w01 = s_set[1 * 128 + pxl];
            float w10 = s_set[2 * 128 + pxl], w11 = s_set[3 * 128 + pxl];
            int i00 = __float_as_int(s_set[4 * 128 + pxl]);
            int i01 = __float_as_int(s_set[5 * 128 + pxl]);
            int i10 = __float_as_int(s_set[6 * 128 + pxl]);
            int i11 = __float_as_int(s_set[7 * 128 + pxl]);
            const float4* q00 = (const float4*)(xb + i00) + cg * 2;
            const float4* q01 = (const float4*)(xb + i01) + cg * 2;
            const float4* q10 = (const float4*)(xb + i10) + cg * 2;
            const float4* q11 = (const float4*)(xb + i11) + cg * 2;
            float4 va, vb2;
            {
                float4 A = q00[0], Bq = q01[0], Cq = q10[0], D = q11[0];
                va.x = fmaf(w11, D.x, fmaf(w10, Cq.x, fmaf(w01, Bq.x, w00 * A.x)));
                va.y = fmaf(w11, D.y, fmaf(w10, Cq.y, fmaf(w01, Bq.y, w00 * A.y)));
                va.z = fmaf(w11, D.z, fmaf(w10, Cq.z, fmaf(w01, Bq.z, w00 * A.z)));
                va.w = fmaf(w11, D.w, fmaf(w10, Cq.w, fmaf(w01, Bq.w, w00 * A.w)));
            }
            {
                float4 A = q00[1], Bq = q01[1], Cq = q10[1], D = q11[1];
                vb2.x = fmaf(w11, D.x, fmaf(w10, Cq.x, fmaf(w01, Bq.x, w00 * A.x)));
                vb2.y = fmaf(w11, D.y, fmaf(w10, Cq.y, fmaf(w01, Bq.y, w00 * A.y)));
                vb2.z = fmaf(w11, D.z, fmaf(w10, Cq.z, fmaf(w01, Bq.z, w00 * A.z)));
                vb2.w = fmaf(w11, D.w, fmaf(w10, Cq.w, fmaf(w01, Bq.w, w00 * A.w)));
            }
            uint4 hq, lq;
            split8(va, vb2, hq, lq);
            int dst = pxl * 128 + ((cg ^ (pxl & 7)) << 4);
            *(uint4*)(smem + SM_AH + dst) = hq;
            *(uint4*)(smem + SM_AL + dst) = lq;
        }
        __syncthreads();
#pragma unroll
        for (int ks = 0; ks < 4; ks++) {
            unsigned ah[2][4], al[2][4];
#pragma unroll
            for (int mi = 0; mi < 2; mi++) {
                int row = w * 32 + mi * 16 + arow;
                unsigned ad = sb + SM_AH + row * 128 + ((((ks << 1) + ahalf) ^ axor) << 4);
                ldsm4(ah[mi], ad);
                ldsm4(al[mi], ad + (SM_AL - SM_AH));
            }
#pragma unroll
            for (int np = 0; np < 4; np++) {
                int rowb = np * 16 + brow;
                unsigned bd = sb + SM_BH + rowb * 128 + ((((ks << 1) + bhalf) ^ axor) << 4);
                unsigned bh[4], bl[4];
                ldsm4(bh, bd);
                ldsm4(bl, bd + (SM_BL - SM_BH));
#pragma unroll
                for (int mi = 0; mi < 2; mi++) {
#pragma unroll
                    for (int nt = 0; nt < 2; nt++) {
                        float* d = acc[mi][np * 2 + nt];
                        mma_bf16(d, ah[mi], bh[2 * nt], bh[2 * nt + 1]);
                        mma_bf16(d, ah[mi], bl[2 * nt], bl[2 * nt + 1]);
                        mma_bf16(d, al[mi], bh[2 * nt], bh[2 * nt + 1]);
                    }
                }
            }
        }
    }

    __syncthreads();
    float* sp = (float*)smem;
#pragma unroll
    for (int mi = 0; mi < 2; mi++)
#pragma unroll
        for (int ni = 0; ni < 8; ni++) {
            int row = w * 32 + mi * 16 + (l >> 2);
            int col = ni * 8 + (l & 3) * 2;
            float b0 = bias[col], b1 = bias[col + 1];
            sp[col * 132 + row]           = acc[mi][ni][0] + b0;
            sp[(col + 1) * 132 + row]     = acc[mi][ni][1] + b1;
            sp[col * 132 + row + 8]       = acc[mi][ni][2] + b0;
            sp[(col + 1) * 132 + row + 8] = acc[mi][ni][3] + b1;
        }
    __syncthreads();
    float* ob = out + (((size_t)b << 6) << 14) + pix0;
#pragma unroll
    for (int it = 0; it < 64; it++) {
        int i = it * 128 + t;
        int oc = i >> 7, px = i & 127;
        ob[((size_t)oc << 14) + px] = sp[oc * 132 + px];
    }
}

extern "C" void kernel_launch(void* const* d_in, const int* in_sizes, int n_in,
                              void* d_out, int out_size) {
    const float* x      = (const float*)d_in[0];
    const float* offw   = (const float*)d_in[1];
    const float* offb   = (const float*)d_in[2];
    const float* weight = (const float*)d_in[3];
    const float* bias   = (const float*)d_in[4];
    float* out = (float*)d_out;

    cudaFuncSetAttribute(k_deform, cudaFuncAttributeMaxDynamicSharedMemorySize,
                         SMEM_TOTAL);

    k_transpose<<<2048, 256>>>(x);
    k_wsplit<<<(KK * OCH * CH + 255) / 256, 256>>>(weight);
    k_owsplit<<<(KK * 32 * CH + 255) / 256, 256>>>(offw);
    k_offmma<<<512, 128>>>(offb);
    k_deform<<<512, 128, SMEM_TOTAL>>>(bias, out);
}

// round 12
// speedup vs baseline: 4.6325x; 1.0060x over previous
#include <cuda_runtime.h>
#include <cuda_bf16.h>
#include <cstdint>

// B=4, C=64, H=W=128, O=64, K=3, pad=1, stride=1
#define BATCH 4
#define CH    64
#define HH    128
#define WW    128
#define HW    16384
#define NPIX  65536
#define OCH   64
#define KK    9

// Scratch (__device__ globals; no cudaMalloc allowed)
__device__ __align__(16) float g_xt[BATCH * HW * CH];            // NHWC x, 16 MB
__device__ __align__(16) float g_off[NPIX * 20];                 // pixel-major offsets
__device__ __align__(16) __nv_bfloat16 g_wbh[KK * OCH * CH];     // deform weight hi [k][oc][c]
__device__ __align__(16) __nv_bfloat16 g_wbl[KK * OCH * CH];     // deform weight lo
__device__ __align__(16) __nv_bfloat16 g_owbh[KK * 32 * CH];     // offset weight hi [k][j(32)][c]
__device__ __align__(16) __nv_bfloat16 g_owbl[KK * 32 * CH];     // offset weight lo

static __device__ __forceinline__ unsigned smem_u32(const void* p) {
    unsigned a;
    asm("{ .reg .u64 t; cvta.to.shared.u64 t, %1; cvt.u32.u64 %0, t; }" : "=r"(a) : "l"(p));
    return a;
}
static __device__ __forceinline__ void ldsm4(unsigned* r, unsigned addr) {
    asm volatile("ldmatrix.sync.aligned.m8n8.x4.shared.b16 {%0,%1,%2,%3}, [%4];"
        : "=r"(r[0]), "=r"(r[1]), "=r"(r[2]), "=r"(r[3]) : "r"(addr));
}
static __device__ __forceinline__ void mma_bf16(float* d, const unsigned* a,
                                                unsigned b0, unsigned b1) {
    asm volatile("mma.sync.aligned.m16n8k16.row.col.f32.bf16.bf16.f32 "
        "{%0,%1,%2,%3}, {%4,%5,%6,%7}, {%8,%9}, {%0,%1,%2,%3};"
        : "+f"(d[0]), "+f"(d[1]), "+f"(d[2]), "+f"(d[3])
        : "r"(a[0]), "r"(a[1]), "r"(a[2]), "r"(a[3]), "r"(b0), "r"(b1));
}
static __device__ __forceinline__ void split8(const float4& a, const float4& b,
                                              uint4& hq, uint4& lq) {
    float vv[8] = {a.x, a.y, a.z, a.w, b.x, b.y, b.z, b.w};
    unsigned* hp = (unsigned*)&hq;
    unsigned* lp = (unsigned*)&lq;
#pragma unroll
    for (int j = 0; j < 4; j++) {
        __nv_bfloat162 h = __floats2bfloat162_rn(vv[2*j], vv[2*j+1]);
        float r0 = vv[2*j]   - __bfloat162float(__low2bfloat16(h));
        float r1 = vv[2*j+1] - __bfloat162float(__high2bfloat16(h));
        __nv_bfloat162 lo2 = __floats2bfloat162_rn(r0, r1);
        hp[j] = *(unsigned*)&h;
        lp[j] = *(unsigned*)&lo2;
    }
}

// ---------------- Kernel 0: NCHW -> NHWC transpose of x ----------------
__global__ void k_transpose(const float* __restrict__ x) {
    __shared__ float tile[8][33];
    int bid = blockIdx.x;
    int b  = bid >> 9;
    int p0 = (bid & 511) << 5;
    int tx = threadIdx.x & 31, ty = threadIdx.x >> 5;
    int cx = threadIdx.x & 7,  pw = threadIdx.x >> 3;
    for (int c0 = 0; c0 < CH; c0 += 8) {
        tile[ty][tx] = x[(((size_t)(b * CH + c0 + ty)) << 14) + p0 + tx];
        __syncthreads();
        g_xt[(((size_t)((b << 14) + p0 + pw)) << 6) + c0 + cx] = tile[cx][pw];
        __syncthreads();
    }
}

// ---------------- Kernel 0b: deform weight split -> bf16 hi/lo, [k][oc][c] ----------------
__global__ void k_wsplit(const float* __restrict__ w) {
    int i = blockIdx.x * 256 + threadIdx.x;
    if (i < KK * OCH * CH) {
        int k = i / (OCH * CH), r = i % (OCH * CH);
        int oc = r >> 6, c = r & 63;
        float v = w[(oc * CH + c) * KK + k];
        __nv_bfloat16 h = __float2bfloat16(v);
        g_wbh[i] = h;
        g_wbl[i] = __float2bfloat16(v - __bfloat162float(h));
    }
}
// offset weight split -> [k][j<32 pad][c]
__global__ void k_owsplit(const float* __restrict__ ow) {
    int i = blockIdx.x * 256 + threadIdx.x;
    if (i < KK * 32 * CH) {
        int k = i / (32 * CH), r = i % (32 * CH);
        int j = r >> 6, c = r & 63;
        float v = (j < 18) ? ow[(j * CH + c) * 9 + k] : 0.f;
        __nv_bfloat16 h = __float2bfloat16(v);
        g_owbh[i] = h;
        g_owbl[i] = __float2bfloat16(v - __bfloat162float(h));
    }
}

// ---------------- Kernel 1: offset conv via HMMA split-bf16 ----------------
#define OS_AH 0
#define OS_AL 16640
#define OS_BH 33280
#define OS_BL 37376
#define OS_TOT 41472

__global__ __launch_bounds__(128, 4) void k_offmma(const float* __restrict__ offb) {
    __shared__ __align__(128) char smem2[OS_TOT];
    unsigned sb = smem_u32(smem2);

    int t = threadIdx.x, l = t & 31, w = t >> 5;
    int bx = blockIdx.x;
    int b  = bx >> 7, y = bx & 127;
    int pix0 = y << 7;

    float acc[2][4][4];
#pragma unroll
    for (int mi = 0; mi < 2; mi++)
#pragma unroll
        for (int ni = 0; ni < 4; ni++)
#pragma unroll
            for (int j = 0; j < 4; j++) acc[mi][ni][j] = 0.f;

    int arow  = (l & 7) | (l & 8);
    int ahalf = (l >> 4) & 1;
    int brow  = (((l >> 4) & 1) << 3) | (l & 7);
    int bhalf = (l >> 3) & 1;

    if (t < 32) {
        int tile = t >> 4;
        int rr   = ((t >> 3) & 1) ? 129 : 0;
        int ch   = t & 7;
        *(uint4*)(smem2 + (tile ? OS_AL : OS_AH) + rr * 128 + ch * 16) =
            make_uint4(0, 0, 0, 0);
    }

#pragma unroll 1
    for (int dyi = 0; dyi < 3; dyi++) {
        int row = y + dyi - 1;
        if ((unsigned)row >= (unsigned)HH) continue;
        __syncthreads();
        const float4* src = (const float4*)g_xt +
                            (((size_t)((b << 14) + (row << 7))) << 4);
#pragma unroll
        for (int it = 0; it < 8; it++) {
            int idx = it * 128 + t;
            int pxl = idx >> 3, ch = idx & 7;
            const float4* s4 = src + pxl * 16 + ch * 2;
            float4 a = s4[0], bq = s4[1];
            uint4 hq, lq;
            split8(a, bq, hq, lq);
            int r1 = pxl + 1;
            int dst = r1 * 128 + ((ch ^ (r1 & 7)) << 4);
            *(uint4*)(smem2 + OS_AH + dst) = hq;
            *(uint4*)(smem2 + OS_AL + dst) = lq;
        }
#pragma unroll 1
        for (int dxi = 0; dxi < 3; dxi++) {
            int k = dyi * 3 + dxi;
            __syncthreads();
            {
                const uint4* bh4 = (const uint4*)(g_owbh + k * (32 * CH));
                const uint4* bl4 = (const uint4*)(g_owbl + k * (32 * CH));
#pragma unroll
                for (int u0 = 0; u0 < 2; u0++) {
                    int u = u0 * 128 + t;
                    int rowb = u >> 3, ch = u & 7;
                    int dst = rowb * 128 + ((ch ^ (rowb & 7)) << 4);
                    *(uint4*)(smem2 + OS_BH + dst) = bh4[u];
                    *(uint4*)(smem2 + OS_BL + dst) = bl4[u];
                }
            }
            __syncthreads();
#pragma unroll
            for (int ks = 0; ks < 4; ks++) {
                unsigned ah[2][4], al[2][4];
#pragma unroll
                for (int mi = 0; mi < 2; mi++) {
                    int tr = w * 32 + mi * 16 + arow + dxi;
                    unsigned ad = sb + OS_AH + tr * 128 +
                                  ((((ks << 1) + ahalf) ^ (tr & 7)) << 4);
                    ldsm4(ah[mi], ad);
                    ldsm4(al[mi], ad + (OS_AL - OS_AH));
                }
#pragma unroll
                for (int np = 0; np < 2; np++) {
                    int rowb = np * 16 + brow;
                    unsigned bd = sb + OS_BH + rowb * 128 +
                                  ((((ks << 1) + bhalf) ^ (rowb & 7)) << 4);
                    unsigned bh[4], bl[4];
                    ldsm4(bh, bd);
                    ldsm4(bl, bd + (OS_BL - OS_BH));
#pragma unroll
                    for (int mi = 0; mi < 2; mi++) {
#pragma unroll
                        for (int nt = 0; nt < 2; nt++) {
                            float* d = acc[mi][np * 2 + nt];
                            mma_bf16(d, ah[mi], bh[2 * nt], bh[2 * nt + 1]);
                            mma_bf16(d, ah[mi], bl[2 * nt], bl[2 * nt + 1]);
                            mma_bf16(d, al[mi], bh[2 * nt], bh[2 * nt + 1]);
                        }
                    }
                }
            }
        }
    }

    __syncthreads();
    float* st = (float*)smem2;
#pragma unroll
    for (int mi = 0; mi < 2; mi++)
#pragma unroll
        for (int ni = 0; ni < 3; ni++) {
            int row0 = w * 32 + mi * 16 + (l >> 2);
            int col  = ni * 8 + (l & 3) * 2;
            if (col < 18) {
                float b0 = offb[col], b1 = offb[col + 1];
                st[row0 * 20 + col]           = acc[mi][ni][0] + b0;
                st[row0 * 20 + col + 1]       = acc[mi][ni][1] + b1;
                st[(row0 + 8) * 20 + col]     = acc[mi][ni][2] + b0;
                st[(row0 + 8) * 20 + col + 1] = acc[mi][ni][3] + b1;
            }
        }
    __syncthreads();
    float4* dst = (float4*)(g_off + (size_t)((b << 14) + pix0) * 20);
    const float4* s4 = (const float4*)st;
#pragma unroll
    for (int it = 0; it < 5; it++)
        dst[it * 128 + t] = s4[it * 128 + t];
}

// ---------------- Kernel 2: deformable conv, 2 rows / CTA, 8 warps ----------------
// Block = 2 image rows (256 px). D[256px, 64oc]; warp = 32px x 64oc.
// smem: A hi 32KB | A lo 32KB | B hi 8KB | B lo 8KB | set 8KB = 88KB -> 2 CTAs/SM.
#define SM_AH   0
#define SM_AL   32768
#define SM_BH   65536
#define SM_BL   73728
#define SM_SET  81920
#define SMEM_TOTAL 90112

__global__ __launch_bounds__(256, 2) void k_deform(const float* __restrict__ bias,
                                                   float* __restrict__ out) {
    extern __shared__ __align__(1024) char smem[];
    unsigned sb = smem_u32(smem);
    float* s_set = (float*)(smem + SM_SET);

    int t = threadIdx.x, l = t & 31, w = t >> 5;
    int bx = blockIdx.x;
    int b  = bx >> 6, y0 = (bx & 63) << 1;
    int pix0 = y0 << 7;          // 256-px span

    const float* xb = g_xt + ((size_t)b << 20);
    const float* offbase = g_off + (size_t)((b << 14) + pix0) * 20;

    float acc[2][8][4];
#pragma unroll
    for (int mi = 0; mi < 2; mi++)
#pragma unroll
        for (int ni = 0; ni < 8; ni++)
#pragma unroll
            for (int j = 0; j < 4; j++) acc[mi][ni][j] = 0.f;

    int arow  = (l & 7) | (l & 8);
    int ahalf = (l >> 4) & 1;
    int brow  = (((l >> 4) & 1) << 3) | (l & 7);
    int bhalf = (l >> 3) & 1;

#pragma unroll 1
    for (int k = 0; k < KK; k++) {
        __syncthreads();
        // ---- bilinear setup: thread = pixel (256 px across 2 rows) ----
        {
            int yy = y0 + (t >> 7), xx = t & 127;
            float2 o = *(const float2*)(offbase + t * 20 + 2 * k);
            float py  = (float)(yy + k / 3 - 1) + o.x;
            float pxf = (float)(xx + k % 3 - 1) + o.y;
            float fy0 = floorf(py), fx0 = floorf(pxf);
            int yA = (int)fy0, xA = (int)fx0;
            int yB = yA + 1,   xB = xA + 1;
            float wy1 = py - fy0, wx1 = pxf - fx0;
            float wy0 = 1.f - wy1, wx0 = 1.f - wx1;
            bool vy0 = (unsigned)yA < (unsigned)HH, vy1 = (unsigned)yB < (unsigned)HH;
            bool vx0 = (unsigned)xA < (unsigned)WW, vx1 = (unsigned)xB < (unsigned)WW;
            s_set[0 * 256 + t] = (vy0 && vx0) ? wy0 * wx0 : 0.f;
            s_set[1 * 256 + t] = (vy0 && vx1) ? wy0 * wx1 : 0.f;
            s_set[2 * 256 + t] = (vy1 && vx0) ? wy1 * wx0 : 0.f;
            s_set[3 * 256 + t] = (vy1 && vx1) ? wy1 * wx1 : 0.f;
            int cy0 = min(max(yA, 0), HH - 1), cy1 = min(max(yB, 0), HH - 1);
            int cx0 = min(max(xA, 0), WW - 1), cx1 = min(max(xB, 0), WW - 1);
            s_set[4 * 256 + t] = __int_as_float(((cy0 << 7) + cx0) << 6);
            s_set[5 * 256 + t] = __int_as_float(((cy0 << 7) + cx1) << 6);
            s_set[6 * 256 + t] = __int_as_float(((cy1 << 7) + cx0) << 6);
            s_set[7 * 256 + t] = __int_as_float(((cy1 << 7) + cx1) << 6);
        }
        // ---- B tiles: 8KB hi + 8KB lo, swizzled (512 uint4 each) ----
        {
            const uint4* srcH = (const uint4*)(g_wbh + k * (OCH * CH));
            const uint4* srcL = (const uint4*)(g_wbl + k * (OCH * CH));
#pragma unroll
            for (int u0 = 0; u0 < 2; u0++) {
                int idx = u0 * 256 + t;
                int row = idx >> 3, ch = idx & 7;
                int dst = row * 128 + ((ch ^ (row & 7)) << 4);
                *(uint4*)(smem + SM_BH + dst) = srcH[idx];
                *(uint4*)(smem + SM_BL + dst) = srcL[idx];
            }
        }
        __syncthreads();
        // ---- gather + blend + bf16 split into swizzled A tiles ----
#pragma unroll
        for (int it = 0; it < 8; it++) {
            int slot = it * 256 + t;
            int pxl = slot >> 3, cg = slot & 7;
            float w00 = s_set[0 * 256 + pxl], w01 = s_set[1 * 256 + pxl];
            float w10 = s_set[2 * 256 + pxl], w11 = s_set[3 * 256 + pxl];
            int i00 = __float_as_int(s_set[4 * 256 + pxl]);
            int i01 = __float_as_int(s_set[5 * 256 + pxl]);
            int i10 = __float_as_int(s_set[6 * 256 + pxl]);
            int i11 = __float_as_int(s_set[7 * 256 + pxl]);
            const float4* q00 = (const float4*)(xb + i00) + cg * 2;
            const float4* q01 = (const float4*)(xb + i01) + cg * 2;
            const float4* q10 = (const float4*)(xb + i10) + cg * 2;
            const float4* q11 = (const float4*)(xb + i11) + cg * 2;
            float4 va, vb2;
            {
                float4 A = q00[0], Bq = q01[0], Cq = q10[0], D = q11[0];
                va.x = fmaf(w11, D.x, fmaf(w10, Cq.x, fmaf(w01, Bq.x, w00 * A.x)));
                va.y = fmaf(w11, D.y, fmaf(w10, Cq.y, fmaf(w01, Bq.y, w00 * A.y)));
                va.z = fmaf(w11, D.z, fmaf(w10, Cq.z, fmaf(w01, Bq.z, w00 * A.z)));
                va.w = fmaf(w11, D.w, fmaf(w10, Cq.w, fmaf(w01, Bq.w, w00 * A.w)));
            }
            {
                float4 A = q00[1], Bq = q01[1], Cq = q10[1], D = q11[1];
                vb2.x = fmaf(w11, D.x, fmaf(w10, Cq.x, fmaf(w01, Bq.x, w00 * A.x)));
                vb2.y = fmaf(w11, D.y, fmaf(w10, Cq.y, fmaf(w01, Bq.y, w00 * A.y)));
                vb2.z = fmaf(w11, D.z, fmaf(w10, Cq.z, fmaf(w01, Bq.z, w00 * A.z)));
                vb2.w = fmaf(w11, D.w, fmaf(w10, Cq.w, fmaf(w01, Bq.w, w00 * A.w)));
            }
            uint4 hq, lq;
            split8(va, vb2, hq, lq);
            int dst = pxl * 128 + ((cg ^ (pxl & 7)) << 4);
            *(uint4*)(smem + SM_AH + dst) = hq;
            *(uint4*)(smem + SM_AL + dst) = lq;
        }
        __syncthreads();
        // ---- tensor passes: AhBh + AhBl + AlBh, K=64 ----
#pragma unroll
        for (int ks = 0; ks < 4; ks++) {
            unsigned ah[2][4], al[2][4];
#pragma unroll
            for (int mi = 0; mi < 2; mi++) {
                int row = w * 32 + mi * 16 + arow;
                unsigned ad = sb + SM_AH + row * 128 +
                              ((((ks << 1) + ahalf) ^ (row & 7)) << 4);
                ldsm4(ah[mi], ad);
                ldsm4(al[mi], ad + (SM_AL - SM_AH));
            }
#pragma unroll
            for (int np = 0; np < 4; np++) {
                int rowb = np * 16 + brow;
                unsigned bd = sb + SM_BH + rowb * 128 +
                              ((((ks << 1) + bhalf) ^ (rowb & 7)) << 4);
                unsigned bh[4], bl[4];
                ldsm4(bh, bd);
                ldsm4(bl, bd + (SM_BL - SM_BH));
#pragma unroll
                for (int mi = 0; mi < 2; mi++) {
#pragma unroll
                    for (int nt = 0; nt < 2; nt++) {
                        float* d = acc[mi][np * 2 + nt];
                        mma_bf16(d, ah[mi], bh[2 * nt], bh[2 * nt + 1]);
                        mma_bf16(d, ah[mi], bl[2 * nt], bl[2 * nt + 1]);
                        mma_bf16(d, al[mi], bh[2 * nt], bh[2 * nt + 1]);
                    }
                }
            }
        }
    }

    // ---- epilogue: regs -> smem [oc][256px] -> coalesced NCHW stores ----
    __syncthreads();
    float* sp = (float*)smem;   // pitch 260 floats
#pragma unroll
    for (int mi = 0; mi < 2; mi++)
#pragma unroll
        for (int ni = 0; ni < 8; ni++) {
            int row = w * 32 + mi * 16 + (l >> 2);
            int col = ni * 8 + (l & 3) * 2;
            float b0 = bias[col], b1 = bias[col + 1];
            sp[col * 260 + row]           = acc[mi][ni][0] + b0;
            sp[(col + 1) * 260 + row]     = acc[mi][ni][1] + b1;
            sp[col * 260 + row + 8]       = acc[mi][ni][2] + b0;
            sp[(col + 1) * 260 + row + 8] = acc[mi][ni][3] + b1;
        }
    __syncthreads();
    float* ob = out + (((size_t)b << 6) << 14) + pix0;
#pragma unroll
    for (int it = 0; it < 64; it++) {
        int i = it * 256 + t;
        int oc = i >> 8, px = i & 255;
        ob[((size_t)oc << 14) + px] = sp[oc * 260 + px];
    }
}

extern "C" void kernel_launch(void* const* d_in, const int* in_sizes, int n_in,
                              void* d_out, int out_size) {
    const float* x      = (const float*)d_in[0];
    const float* offw   = (const float*)d_in[1];
    const float* offb   = (const float*)d_in[2];
    const float* weight = (const float*)d_in[3];
    const float* bias   = (const float*)d_in[4];
    float* out = (float*)d_out;

    cudaFuncSetAttribute(k_deform, cudaFuncAttributeMaxDynamicSharedMemorySize,
                         SMEM_TOTAL);

    k_transpose<<<2048, 256>>>(x);
    k_wsplit<<<(KK * OCH * CH + 255) / 256, 256>>>(weight);
    k_owsplit<<<(KK * 32 * CH + 255) / 256, 256>>>(offw);
    k_offmma<<<512, 128>>>(offb);
    k_deform<<<256, 256, SMEM_TOTAL>>>(bias, out);
}